// round 16
// baseline (speedup 1.0000x reference)
#include <cuda_runtime.h>
#include <math.h>

#define Bsz 2
#define Dm  128
#define Nn  2048
#define Hh  4
#define Zs  4
#define ZH  16
typedef unsigned long long u64;

__device__ float g_x [Zs*Dm*Nn];
__device__ float g_s [Zs*Dm*Nn];
__device__ float g_q [Zs*Dm*Nn];
__device__ float g_k [Zs*Dm*Nn];
__device__ float g_v [Zs*Dm*Nn];
__device__ float g_sc[(size_t)ZH*Nn*Nn];
__device__ float g_pm[ZH*16*Nn];
__device__ float g_pz[ZH*16*Nn];
__device__ float g_msg[Zs*Dm*Nn];
__device__ float g_h [Zs*2*Dm*Nn];
__device__ float g_impp[ZH*16*Nn];
__device__ float g_imp[Zs*Nn];
__device__ int   g_idx[Zs*Nn];
__device__ int   g_flag[Zs*Nn];
__device__ float g_wc[4*256*128];
__device__ float g_bc[4*256];
__device__ float g_hpsum[Zs*256*16];
__device__ float g_hpsq [Zs*256*16];

__device__ __forceinline__ u64 ffma2(u64 a, u64 b, u64 c) {
    u64 d; asm("fma.rn.f32x2 %0, %1, %2, %3;" : "=l"(d) : "l"(a), "l"(b), "l"(c)); return d;
}
__device__ __forceinline__ u64 dupf(float x) {
    u64 d; unsigned xi = __float_as_uint(x);
    asm("mov.b64 %0, {%1, %2};" : "=l"(d) : "r"(xi), "r"(xi)); return d;
}
__device__ __forceinline__ float2 unpk(u64 v) {
    unsigned lo, hi; asm("mov.b64 {%0, %1}, %2;" : "=r"(lo), "=r"(hi) : "l"(v));
    return make_float2(__uint_as_float(lo), __uint_as_float(hi));
}

__global__ void copyf4_kernel(const float4* __restrict__ s, float4* __restrict__ d, int n4)
{ int g = blockIdx.x*256 + threadIdx.x; if (g < n4) d[g] = s[g]; }

__global__ void init_kernel(const float4* __restrict__ x0, const float4* __restrict__ x1,
                            float4* __restrict__ x, int* __restrict__ idx)
{
    int g = blockIdx.x*256 + threadIdx.x;
    x[g] = x0[g];
    x[g + Bsz*Dm*Nn/4] = x1[g];
    if (g < Zs*Nn) idx[g] = g % Nn;
}

__global__ void gather_kernel(const float* __restrict__ x, const int* __restrict__ idx,
                              float* __restrict__ s, int K, int cross)
{
    int g = blockIdx.x*256 + threadIdx.x;
    if (g >= Zs*Dm*K) return;
    int z = g / (Dm*K), r = g - z*(Dm*K);
    int d = r / K, kk = r - d*K;
    int zs = (((z>>1) ^ cross) << 1) | (z & 1);
    s[g] = x[(size_t)zs*Dm*Nn + (size_t)d*Nn + idx[zs*Nn + kk]];
}

// ---------------- core 128co x 128n GEMM, BK=32 ----------------
__device__ __forceinline__ void pw3_core(
    const float* W, const float* X,
    const float* bias, float* Y, int Ncols, int n0)
{
    __shared__ float As[32][132];
    __shared__ float Bs[32][132];
    int tid = threadIdx.x, ty = tid >> 4, tx = tid & 15;
    u64 acc[8][4];
    #pragma unroll
    for (int i = 0; i < 8; i++) { acc[i][0]=0; acc[i][1]=0; acc[i][2]=0; acc[i][3]=0; }

    for (int kt = 0; kt < Dm; kt += 32) {
        #pragma unroll
        for (int j = 0; j < 4; j++) {
            int e = tid + 256*j, r = e >> 3, kq = e & 7;
            float4 w4 = *(const float4*)&W[(size_t)r*Dm + kt + kq*4];
            As[kq*4+0][r]=w4.x; As[kq*4+1][r]=w4.y; As[kq*4+2][r]=w4.z; As[kq*4+3][r]=w4.w;
        }
        #pragma unroll
        for (int j = 0; j < 4; j++) {
            int e = tid + 256*j, kr = e >> 5, c4 = e & 31;
            *(float4*)&Bs[kr][c4*4] = *(const float4*)&X[(size_t)(kt+kr)*Ncols + n0 + c4*4];
        }
        __syncthreads();
        #pragma unroll
        for (int kk = 0; kk < 32; kk++) {
            float4 a0 = *(const float4*)&As[kk][ty*8];
            float4 a1 = *(const float4*)&As[kk][ty*8+4];
            ulonglong2 bA = *(const ulonglong2*)&Bs[kk][tx*8];
            ulonglong2 bB = *(const ulonglong2*)&Bs[kk][tx*8+4];
            float ar[8] = {a0.x,a0.y,a0.z,a0.w,a1.x,a1.y,a1.z,a1.w};
            #pragma unroll
            for (int r = 0; r < 8; r++) {
                u64 a2 = dupf(ar[r]);
                acc[r][0] = ffma2(a2, bA.x, acc[r][0]);
                acc[r][1] = ffma2(a2, bA.y, acc[r][1]);
                acc[r][2] = ffma2(a2, bB.x, acc[r][2]);
                acc[r][3] = ffma2(a2, bB.y, acc[r][3]);
            }
        }
        __syncthreads();
    }
    #pragma unroll
    for (int r = 0; r < 8; r++) {
        int row = ty*8 + r;
        float bi = bias[row];
        float2 o0=unpk(acc[r][0]), o1=unpk(acc[r][1]), o2=unpk(acc[r][2]), o3=unpk(acc[r][3]);
        float4 u = make_float4(o0.x+bi, o0.y+bi, o1.x+bi, o1.y+bi);
        float4 w = make_float4(o2.x+bi, o2.y+bi, o3.x+bi, o3.y+bi);
        float* dst = Y + (size_t)row*Ncols + n0 + tx*8;
        *(float4*)dst = u; *(float4*)(dst+4) = w;
    }
}

// merged q/k/v projection. grid (Nn/128, 1, 12), forced 2 blocks/SM
__global__ void __launch_bounds__(256, 2) qkv_kernel(
    const float* __restrict__ Wq, const float* __restrict__ bq,
    const float* __restrict__ Wk, const float* __restrict__ bk,
    const float* __restrict__ Wv, const float* __restrict__ bv,
    const float* __restrict__ x, const float* __restrict__ s,
    float* __restrict__ q, float* __restrict__ k, float* __restrict__ v, int K)
{
    int which = blockIdx.z >> 2, z = blockIdx.z & 3;
    int n0 = blockIdx.x*128;
    const float *W, *bias, *X; float* Y; int NC;
    if (which == 0)      { W=Wq; bias=bq; X=x+(size_t)z*Dm*Nn; Y=q+(size_t)z*Dm*Nn; NC=Nn; }
    else if (which == 1) { if (n0 >= K) return; W=Wk; bias=bk; X=s+(size_t)z*Dm*K; Y=k+(size_t)z*Dm*K; NC=K; }
    else                 { if (n0 >= K) return; W=Wv; bias=bv; X=s+(size_t)z*Dm*K; Y=v+(size_t)z*Dm*K; NC=K; }
    pw3_core(W, X, bias, Y, NC, n0);
}

// Wc[l] = W1b[l] @ Wm[l].  grid (1, 4, 4), 64co x 128n
__global__ void __launch_bounds__(256) wc_kernel(
    const float* __restrict__ W1, const float* __restrict__ Wm, float* __restrict__ wc)
{
    __shared__ float As[32][68];
    __shared__ float Bs[32][132];
    int l = blockIdx.z, co0 = blockIdx.y*64;
    const float* W = W1 + (size_t)l*2*Dm*2*Dm + Dm;
    const float* X = Wm + (size_t)l*Dm*Dm;
    float* Y = wc + (size_t)l*2*Dm*Dm;
    int tid = threadIdx.x, ty = tid >> 4, tx = tid & 15;
    u64 c2[4][4];
    #pragma unroll
    for (int i = 0; i < 4; i++) { c2[i][0]=0; c2[i][1]=0; c2[i][2]=0; c2[i][3]=0; }
    for (int kt = 0; kt < Dm; kt += 32) {
        #pragma unroll
        for (int j = 0; j < 2; j++) {
            int e = tid + 256*j, r = e >> 3, kq = e & 7;
            float4 w4 = *(const float4*)&W[(size_t)(co0+r)*2*Dm + kt + kq*4];
            As[kq*4+0][r]=w4.x; As[kq*4+1][r]=w4.y; As[kq*4+2][r]=w4.z; As[kq*4+3][r]=w4.w;
        }
        #pragma unroll
        for (int j = 0; j < 4; j++) {
            int e = tid + 256*j, kr = e >> 5, c4 = e & 31;
            *(float4*)&Bs[kr][c4*4] = *(const float4*)&X[(size_t)(kt+kr)*Dm + c4*4];
        }
        __syncthreads();
        #pragma unroll
        for (int kk = 0; kk < 32; kk++) {
            float4 a4 = *(const float4*)&As[kk][ty*4];
            ulonglong2 bA = *(const ulonglong2*)&Bs[kk][tx*8];
            ulonglong2 bB = *(const ulonglong2*)&Bs[kk][tx*8+4];
            float ar[4] = {a4.x, a4.y, a4.z, a4.w};
            #pragma unroll
            for (int r = 0; r < 4; r++) {
                u64 a2 = dupf(ar[r]);
                c2[r][0] = ffma2(a2, bA.x, c2[r][0]);
                c2[r][1] = ffma2(a2, bA.y, c2[r][1]);
                c2[r][2] = ffma2(a2, bB.x, c2[r][2]);
                c2[r][3] = ffma2(a2, bB.y, c2[r][3]);
            }
        }
        __syncthreads();
    }
    #pragma unroll
    for (int r = 0; r < 4; r++) {
        int row = co0 + ty*4 + r;
        float2 o0=unpk(c2[r][0]), o1=unpk(c2[r][1]), o2=unpk(c2[r][2]), o3=unpk(c2[r][3]);
        float* dst = Y + (size_t)row*Dm + tx*8;
        *(float4*)dst     = make_float4(o0.x, o0.y, o1.x, o1.y);
        *(float4*)(dst+4) = make_float4(o2.x, o2.y, o3.x, o3.y);
    }
}

__global__ void bc_kernel(const float* __restrict__ W1, const float* __restrict__ bm,
                          const float* __restrict__ b1, float* __restrict__ bc)
{
    int l = blockIdx.x, o = threadIdx.x;
    const float* wrow = W1 + (size_t)l*2*Dm*2*Dm + (size_t)o*2*Dm + Dm;
    const float* bml = bm + l*Dm;
    float s = b1[l*2*Dm + o];
    #pragma unroll 4
    for (int j = 0; j < Dm; j++) s += wrow[j]*bml[j];
    bc[l*2*Dm + o] = s;
}

// h_pre = W1a@x + Wc@msg + bc with per-row (sum, sumsq) partials. grid (Nn/128, 2, Zs)
__global__ void __launch_bounds__(256) w1dual_kernel(
    const float* __restrict__ W1, const float* __restrict__ Wc,
    const float* __restrict__ bc,
    const float* __restrict__ x, const float* __restrict__ msg, float* __restrict__ h,
    float* __restrict__ hpsum, float* __restrict__ hpsq)
{
    __shared__ float As[32][132];
    __shared__ float Bs[32][132];
    __shared__ float redS[128][17];
    __shared__ float redQ[128][17];
    int z = blockIdx.z, co0 = blockIdx.y*128, n0 = blockIdx.x*128;
    const float* Xa = x   + (size_t)z*Dm*Nn;
    const float* Xb = msg + (size_t)z*Dm*Nn;
    float* Y = h + (size_t)z*2*Dm*Nn;
    int tid = threadIdx.x, ty = tid >> 4, tx = tid & 15;
    u64 acc[8][4];
    #pragma unroll
    for (int i = 0; i < 8; i++) { acc[i][0]=0; acc[i][1]=0; acc[i][2]=0; acc[i][3]=0; }

    for (int kt = 0; kt < 2*Dm; kt += 32) {
        const float* W = (kt < Dm) ? W1 : Wc;
        const float* X = (kt < Dm) ? Xa : Xb;
        int ws = (kt < Dm) ? 2*Dm : Dm;
        int kl = (kt < Dm) ? kt : (kt - Dm);
        #pragma unroll
        for (int j = 0; j < 4; j++) {
            int e = tid + 256*j, r = e >> 3, kq = e & 7;
            float4 w4 = *(const float4*)&W[(size_t)(co0+r)*ws + kl + kq*4];
            As[kq*4+0][r]=w4.x; As[kq*4+1][r]=w4.y; As[kq*4+2][r]=w4.z; As[kq*4+3][r]=w4.w;
        }
        #pragma unroll
        for (int j = 0; j < 4; j++) {
            int e = tid + 256*j, kr = e >> 5, c4 = e & 31;
            *(float4*)&Bs[kr][c4*4] = *(const float4*)&X[(size_t)(kl+kr)*Nn + n0 + c4*4];
        }
        __syncthreads();
        #pragma unroll
        for (int kk = 0; kk < 32; kk++) {
            float4 a0 = *(const float4*)&As[kk][ty*8];
            float4 a1 = *(const float4*)&As[kk][ty*8+4];
            ulonglong2 bA = *(const ulonglong2*)&Bs[kk][tx*8];
            ulonglong2 bB = *(const ulonglong2*)&Bs[kk][tx*8+4];
            float ar[8] = {a0.x,a0.y,a0.z,a0.w,a1.x,a1.y,a1.z,a1.w};
            #pragma unroll
            for (int r = 0; r < 8; r++) {
                u64 a2 = dupf(ar[r]);
                acc[r][0] = ffma2(a2, bA.x, acc[r][0]);
                acc[r][1] = ffma2(a2, bA.y, acc[r][1]);
                acc[r][2] = ffma2(a2, bB.x, acc[r][2]);
                acc[r][3] = ffma2(a2, bB.y, acc[r][3]);
            }
        }
        __syncthreads();
    }
    #pragma unroll
    for (int r = 0; r < 8; r++) {
        int row = co0 + ty*8 + r;
        float bi = bc[row];
        float2 o0=unpk(acc[r][0]), o1=unpk(acc[r][1]), o2=unpk(acc[r][2]), o3=unpk(acc[r][3]);
        float4 u = make_float4(o0.x+bi, o0.y+bi, o1.x+bi, o1.y+bi);
        float4 w = make_float4(o2.x+bi, o2.y+bi, o3.x+bi, o3.y+bi);
        float* dst = Y + (size_t)row*Nn + n0 + tx*8;
        *(float4*)dst = u; *(float4*)(dst+4) = w;
        float ss = u.x+u.y+u.z+u.w + w.x+w.y+w.z+w.w;
        float qq = u.x*u.x+u.y*u.y+u.z*u.z+u.w*u.w + w.x*w.x+w.y*w.y+w.z*w.z+w.w*w.w;
        redS[ty*8+r][tx] = ss;
        redQ[ty*8+r][tx] = qq;
    }
    __syncthreads();
    if (tid < 128) {
        float ss = 0.f, qq = 0.f;
        #pragma unroll
        for (int t = 0; t < 16; t++) { ss += redS[tid][t]; qq += redQ[tid][t]; }
        int row = co0 + tid;
        hpsum[((size_t)z*256 + row)*16 + blockIdx.x] = ss;
        hpsq [((size_t)z*256 + row)*16 + blockIdx.x] = qq;
    }
}

// x += W2 @ relu((h-mean)*rs) + b2, inline stat finalize. grid (Nn/128, 2, Zs)
__global__ void __launch_bounds__(256) w2norm_kernel(
    const float* __restrict__ W2, const float* __restrict__ b2,
    const float* __restrict__ h, const float* __restrict__ hpsum,
    const float* __restrict__ hpsq, float* __restrict__ x)
{
    __shared__ float As[32][68];
    __shared__ float Bs[32][132];
    __shared__ float sMean[256], sRs[256];
    int z = blockIdx.z;
    const float* Xb = h + (size_t)z*2*Dm*Nn;
    float*       Yb = x + (size_t)z*Dm*Nn;
    int co0 = blockIdx.y*64, n0 = blockIdx.x*128;
    int tid = threadIdx.x, ty = tid >> 4, tx = tid & 15;
    {
        const float* ps = hpsum + ((size_t)z*256 + tid)*16;
        const float* pq = hpsq  + ((size_t)z*256 + tid)*16;
        float ss = 0.f, qq = 0.f;
        #pragma unroll
        for (int t = 0; t < 16; t++) { ss += ps[t]; qq += pq[t]; }
        float mean = ss * (1.0f/Nn);
        sMean[tid] = mean;
        sRs[tid]   = rsqrtf(qq*(1.0f/Nn) - mean*mean + 1e-3f);
    }
    __syncthreads();
    u64 c2[4][4];
    #pragma unroll
    for (int i = 0; i < 4; i++) { c2[i][0]=0; c2[i][1]=0; c2[i][2]=0; c2[i][3]=0; }
    for (int kt = 0; kt < 2*Dm; kt += 32) {
        #pragma unroll
        for (int j = 0; j < 2; j++) {
            int e = tid + 256*j, r = e >> 3, kq = e & 7;
            float4 w4 = *(const float4*)&W2[(size_t)(co0+r)*2*Dm + kt + kq*4];
            As[kq*4+0][r]=w4.x; As[kq*4+1][r]=w4.y; As[kq*4+2][r]=w4.z; As[kq*4+3][r]=w4.w;
        }
        #pragma unroll
        for (int j = 0; j < 4; j++) {
            int e = tid + 256*j, kr = e >> 5, c4 = e & 31;
            int hrow = kt + kr;
            float4 raw = *(const float4*)&Xb[(size_t)hrow*Nn + n0 + c4*4];
            float mean = sMean[hrow], rs = sRs[hrow];
            Bs[kr][c4*4+0] = fmaxf((raw.x-mean)*rs, 0.f);
            Bs[kr][c4*4+1] = fmaxf((raw.y-mean)*rs, 0.f);
            Bs[kr][c4*4+2] = fmaxf((raw.z-mean)*rs, 0.f);
            Bs[kr][c4*4+3] = fmaxf((raw.w-mean)*rs, 0.f);
        }
        __syncthreads();
        #pragma unroll
        for (int kk = 0; kk < 32; kk++) {
            float4 a4 = *(const float4*)&As[kk][ty*4];
            ulonglong2 bA = *(const ulonglong2*)&Bs[kk][tx*8];
            ulonglong2 bB = *(const ulonglong2*)&Bs[kk][tx*8+4];
            float ar[4] = {a4.x, a4.y, a4.z, a4.w};
            #pragma unroll
            for (int r = 0; r < 4; r++) {
                u64 a2 = dupf(ar[r]);
                c2[r][0] = ffma2(a2, bA.x, c2[r][0]);
                c2[r][1] = ffma2(a2, bA.y, c2[r][1]);
                c2[r][2] = ffma2(a2, bB.x, c2[r][2]);
                c2[r][3] = ffma2(a2, bB.y, c2[r][3]);
            }
        }
        __syncthreads();
    }
    #pragma unroll
    for (int r = 0; r < 4; r++) {
        int row = co0 + ty*4 + r;
        float bi = b2[row];
        float2 o0=unpk(c2[r][0]), o1=unpk(c2[r][1]), o2=unpk(c2[r][2]), o3=unpk(c2[r][3]);
        float4 u = make_float4(o0.x+bi, o0.y+bi, o1.x+bi, o1.y+bi);
        float4 w = make_float4(o2.x+bi, o2.y+bi, o3.x+bi, o3.y+bi);
        float* dst = Yb + (size_t)row*Nn + n0 + tx*8;
        float4 e0 = *(float4*)dst, e1 = *(float4*)(dst+4);
        u.x+=e0.x; u.y+=e0.y; u.z+=e0.z; u.w+=e0.w;
        w.x+=e1.x; w.y+=e1.y; w.z+=e1.z; w.w+=e1.w;
        *(float4*)dst = u; *(float4*)(dst+4) = w;
    }
}

// scores: 128n x 128k tile; stores exp numerators + (m_tile, sumexp)
__global__ void __launch_bounds__(256) scores2_kernel(
    const float* __restrict__ q, const float* __restrict__ kbuf,
    float* __restrict__ sc, float* __restrict__ pm, float* __restrict__ pz, int K)
{
    __shared__ float Qs[32][128];
    __shared__ float Ks[32][128];
    __shared__ float red[128][17];
    __shared__ float rowm[128];
    int zh = blockIdx.z, z = zh >> 2, h = zh & 3;
    int n0 = blockIdx.y*128, k0 = blockIdx.x*128;
    const float* qb = q    + (size_t)z*Dm*Nn;
    const float* kb = kbuf + (size_t)z*Dm*K;
    int tid = threadIdx.x;
    #pragma unroll
    for (int j = 0; j < 4; j++) {
        int e = tid + 256*j, i = e >> 5, c4 = e & 31;
        *(float4*)&Qs[i][c4*4] = *(const float4*)&qb[(size_t)(i*4+h)*Nn + n0 + c4*4];
        *(float4*)&Ks[i][c4*4] = *(const float4*)&kb[(size_t)(i*4+h)*K  + k0 + c4*4];
    }
    __syncthreads();
    int ty = tid >> 4, tx = tid & 15, r0 = ty*8, c0 = tx*8;
    u64 acc[8][4];
    #pragma unroll
    for (int i = 0; i < 8; i++) { acc[i][0]=0; acc[i][1]=0; acc[i][2]=0; acc[i][3]=0; }
    #pragma unroll
    for (int i = 0; i < 32; i++) {
        float4 a0 = *(const float4*)&Qs[i][r0];
        float4 a1 = *(const float4*)&Qs[i][r0+4];
        ulonglong2 bA = *(const ulonglong2*)&Ks[i][c0];
        ulonglong2 bB = *(const ulonglong2*)&Ks[i][c0+4];
        float ar[8] = {a0.x,a0.y,a0.z,a0.w,a1.x,a1.y,a1.z,a1.w};
        #pragma unroll
        for (int r = 0; r < 8; r++) {
            u64 a2 = dupf(ar[r]);
            acc[r][0] = ffma2(a2, bA.x, acc[r][0]);
            acc[r][1] = ffma2(a2, bA.y, acc[r][1]);
            acc[r][2] = ffma2(a2, bB.x, acc[r][2]);
            acc[r][3] = ffma2(a2, bB.y, acc[r][3]);
        }
    }
    const float scale = 0.17677669529663687f;
    float* scb = sc + (size_t)zh*Nn*K;
    float vals[8][8], vmax[8];
    #pragma unroll
    for (int r = 0; r < 8; r++) {
        float2 p0=unpk(acc[r][0]), p1=unpk(acc[r][1]), p2=unpk(acc[r][2]), p3=unpk(acc[r][3]);
        vals[r][0]=p0.x*scale; vals[r][1]=p0.y*scale; vals[r][2]=p1.x*scale; vals[r][3]=p1.y*scale;
        vals[r][4]=p2.x*scale; vals[r][5]=p2.y*scale; vals[r][6]=p3.x*scale; vals[r][7]=p3.y*scale;
        float m = vals[r][0];
        #pragma unroll
        for (int c = 1; c < 8; c++) m = fmaxf(m, vals[r][c]);
        vmax[r] = m;
    }
    #pragma unroll
    for (int r = 0; r < 8; r++) red[r0+r][tx] = vmax[r];
    __syncthreads();
    if (tid < 128) {
        float m = red[tid][0];
        #pragma unroll
        for (int t = 1; t < 16; t++) m = fmaxf(m, red[tid][t]);
        rowm[tid] = m;
    }
    __syncthreads();
    #pragma unroll
    for (int r = 0; r < 8; r++) {
        float m = rowm[r0+r], s = 0.0f;
        float ev[8];
        #pragma unroll
        for (int c = 0; c < 8; c++) { ev[c] = expf(vals[r][c] - m); s += ev[c]; }
        float* dst = scb + (size_t)(n0+r0+r)*K + k0 + c0;
        *(float4*)dst     = make_float4(ev[0],ev[1],ev[2],ev[3]);
        *(float4*)(dst+4) = make_float4(ev[4],ev[5],ev[6],ev[7]);
        red[r0+r][tx] = s;
    }
    __syncthreads();
    if (tid < 128) {
        float s = 0.0f;
        #pragma unroll
        for (int t = 0; t < 16; t++) s += red[tid][t];
        size_t po = ((size_t)zh*gridDim.x + blockIdx.x)*Nn + n0 + tid;
        pm[po] = rowm[tid]; pz[po] = s;
    }
}

// msg + inline combine + importance; 256 threads with in-block split-K
__global__ void __launch_bounds__(256) msg5_kernel(
    const float* __restrict__ sc, const float* __restrict__ v,
    const float* __restrict__ pm, const float* __restrict__ pz,
    float* __restrict__ msg, float* __restrict__ impp, int K, int doimp)
{
    __shared__ float Ps[128][36];
    __shared__ float Vs[32][36];
    __shared__ float cred[32][8][4];
    __shared__ float sf[128][17];
    int zh = blockIdx.y, z = zh >> 2, h = zh & 3;
    int n0 = blockIdx.x*128;
    int tid = threadIdx.x;
    int PT = K >> 7;
    const float* scb = sc + (size_t)zh*Nn*K;
    const float* vb  = v  + (size_t)z*Dm*K;
    if (tid < 128) {
        float m = -1e30f;
        for (int pt = 0; pt < PT; pt++)
            m = fmaxf(m, pm[((size_t)zh*PT + pt)*Nn + n0 + tid]);
        float s = 0.0f;
        for (int pt = 0; pt < PT; pt++)
            s += pz[((size_t)zh*PT + pt)*Nn + n0 + tid] *
                 expf(pm[((size_t)zh*PT + pt)*Nn + n0 + tid] - m);
        float iz = 1.0f / s;
        for (int pt = 0; pt < PT; pt++)
            sf[tid][pt] = expf(pm[((size_t)zh*PT + pt)*Nn + n0 + tid] - m) * iz;
    }
    __syncthreads();
    int rg = tid >> 3, k8 = tid & 7;
    int lt = tid & 127, kh = tid >> 7;
    int ty = lt >> 2, tx = lt & 3;
    u64 c2[4][4];
    #pragma unroll
    for (int i = 0; i < 4; i++) { c2[i][0]=0; c2[i][1]=0; c2[i][2]=0; c2[i][3]=0; }

    for (int kc = 0; kc < K; kc += 32) {
        int pt = kc >> 7;
        float cs0=0.f, cs1=0.f, cs2=0.f, cs3=0.f;
        #pragma unroll
        for (int j = 0; j < 4; j++) {
            int row = rg + 32*j;
            float4 s4 = *(const float4*)&scb[(size_t)(n0+row)*K + kc + k8*4];
            float f = sf[row][pt];
            float p0 = s4.x*f, p1 = s4.y*f, p2 = s4.z*f, p3 = s4.w*f;
            *(float4*)&Ps[row][k8*4] = make_float4(p0,p1,p2,p3);
            cs0 += p0; cs1 += p1; cs2 += p2; cs3 += p3;
        }
        if (doimp) {
            cred[rg][k8][0]=cs0; cred[rg][k8][1]=cs1; cred[rg][k8][2]=cs2; cred[rg][k8][3]=cs3;
        }
        {
            int d = tid >> 3, kq = tid & 7;
            float4 v4 = *(const float4*)&vb[(size_t)(d*4+h)*K + kc + kq*4];
            Vs[kq*4+0][d]=v4.x; Vs[kq*4+1][d]=v4.y; Vs[kq*4+2][d]=v4.z; Vs[kq*4+3][d]=v4.w;
        }
        __syncthreads();
        if (doimp && tid < 32) {
            float ssum = 0.0f;
            #pragma unroll
            for (int g2 = 0; g2 < 32; g2++) ssum += cred[g2][tid>>2][tid&3];
            impp[((size_t)zh*(Nn/128) + blockIdx.x)*K + kc + tid] = ssum;
        }
        #pragma unroll
        for (int kk4 = 0; kk4 < 4; kk4++) {
            int k4 = kh*4 + kk4;
            ulonglong2 va[4], vb2[4];
            #pragma unroll
            for (int c = 0; c < 4; c++) {
                va[c]  = *(const ulonglong2*)&Vs[k4*4+c][tx*8];
                vb2[c] = *(const ulonglong2*)&Vs[k4*4+c][tx*8+4];
            }
            #pragma unroll
            for (int r = 0; r < 4; r++) {
                float4 pr = *(const float4*)&Ps[ty + 32*r][k4*4];
                float pv[4] = {pr.x, pr.y, pr.z, pr.w};
                #pragma unroll
                for (int c = 0; c < 4; c++) {
                    u64 a2 = dupf(pv[c]);
                    c2[r][0] = ffma2(a2, va[c].x,  c2[r][0]);
                    c2[r][1] = ffma2(a2, va[c].y,  c2[r][1]);
                    c2[r][2] = ffma2(a2, vb2[c].x, c2[r][2]);
                    c2[r][3] = ffma2(a2, vb2[c].y, c2[r][3]);
                }
            }
        }
        __syncthreads();
    }
    float* mbuf = &Ps[0][0];
    if (kh == 1) {
        #pragma unroll
        for (int r = 0; r < 4; r++)
            #pragma unroll
            for (int c = 0; c < 4; c++) {
                float2 p = unpk(c2[r][c]);
                mbuf[lt*33 + (r*4+c)*2 + 0] = p.x;
                mbuf[lt*33 + (r*4+c)*2 + 1] = p.y;
            }
    }
    __syncthreads();
    if (kh == 0) {
        #pragma unroll
        for (int r = 0; r < 4; r++) {
            float2 q0=unpk(c2[r][0]), q1=unpk(c2[r][1]), q2=unpk(c2[r][2]), q3=unpk(c2[r][3]);
            float ov[8] = {q0.x,q0.y,q1.x,q1.y,q2.x,q2.y,q3.x,q3.y};
            #pragma unroll
            for (int c = 0; c < 8; c++) {
                float oth = mbuf[lt*33 + (r*4 + (c>>1))*2 + (c&1)];
                int d = (tx*8 + c)*4 + h;
                msg[(size_t)z*Dm*Nn + (size_t)d*Nn + n0 + ty + 32*r] = ov[c] + oth;
            }
        }
    }
}

__global__ void impreduce_kernel(const float* __restrict__ impp, float* __restrict__ imp, int K)
{
    int g = blockIdx.x*256 + threadIdx.x;
    if (g >= Zs*K) return;
    int z = g / K, k = g - z*K;
    float s = 0.0f;
    for (int h = 0; h < Hh; h++)
        for (int nb = 0; nb < Nn/128; nb++)
            s += impp[((size_t)((z*4+h)*(Nn/128) + nb))*K + k];
    imp[z*Nn + k] = s;
}

__global__ void rankflag_kernel(const float* __restrict__ imp, int* __restrict__ flag,
                                int K, int kkeep)
{
    __shared__ float sp[2048];
    int z = blockIdx.y;
    int tid = threadIdx.x;
    int pos = blockIdx.x*128 + tid;
    for (int j = tid; j < K; j += 128) sp[j] = imp[z*Nn + j];
    __syncthreads();
    float vv = sp[pos];
    int r = 0;
    for (int j = 0; j < K; j++) {
        float u = sp[j];
        r += (u > vv) || (u == vv && j < pos);
    }
    flag[z*Nn + pos] = (r < kkeep) ? 1 : 0;
}

__global__ void compact_kernel(const int* __restrict__ flag, int* __restrict__ idx,
                               int K, int cross)
{
    __shared__ int sflag[2048];
    __shared__ int sidx[2048];
    __shared__ int scnt[256];
    int z = blockIdx.x;
    int tz = (((z>>1) ^ cross) << 1) | (z & 1);
    int* ix = idx + (size_t)tz*Nn;
    int tid = threadIdx.x;
    for (int j = tid; j < K; j += 256) { sflag[j] = flag[z*Nn + j]; sidx[j] = ix[j]; }
    __syncthreads();
    int chunk = K >> 8;
    int base = tid*chunk, c = 0;
    for (int t = 0; t < chunk; t++) c += sflag[base + t];
    scnt[tid] = c;
    __syncthreads();
    if (tid == 0) {
        int a = 0;
        for (int i = 0; i < 256; i++) { int t = scnt[i]; scnt[i] = a; a += t; }
    }
    __syncthreads();
    int o = scnt[tid];
    for (int t = 0; t < chunk; t++)
        if (sflag[base + t]) ix[o++] = sidx[base + t];
}

extern "C" void kernel_launch(void* const* d_in, const int* in_sizes, int n_in,
                              void* d_out, int out_size)
{
    const float* x0in = (const float*)d_in[0];
    const float* x1in = (const float*)d_in[1];
    const float* Wq = (const float*)d_in[2];  const float* bq = (const float*)d_in[3];
    const float* Wk = (const float*)d_in[4];  const float* bk = (const float*)d_in[5];
    const float* Wv = (const float*)d_in[6];  const float* bv = (const float*)d_in[7];
    const float* Wm = (const float*)d_in[8];  const float* bm = (const float*)d_in[9];
    const float* W1 = (const float*)d_in[10]; const float* b1 = (const float*)d_in[11];
    const float* W2 = (const float*)d_in[12]; const float* b2 = (const float*)d_in[13];
    float* out = (float*)d_out;

    float *x,*s,*q,*k,*v,*sc,*pm,*pz,*msg,*h,*impp,*imp,*wc,*bc,*hpsum,*hpsq;
    int *idx,*flag;
    cudaGetSymbolAddress((void**)&x, g_x);   cudaGetSymbolAddress((void**)&s, g_s);
    cudaGetSymbolAddress((void**)&q, g_q);   cudaGetSymbolAddress((void**)&k, g_k);
    cudaGetSymbolAddress((void**)&v, g_v);   cudaGetSymbolAddress((void**)&sc, g_sc);
    cudaGetSymbolAddress((void**)&pm, g_pm); cudaGetSymbolAddress((void**)&pz, g_pz);
    cudaGetSymbolAddress((void**)&msg, g_msg);
    cudaGetSymbolAddress((void**)&h, g_h);   cudaGetSymbolAddress((void**)&impp, g_impp);
    cudaGetSymbolAddress((void**)&imp, g_imp); cudaGetSymbolAddress((void**)&idx, g_idx);
    cudaGetSymbolAddress((void**)&flag, g_flag);
    cudaGetSymbolAddress((void**)&wc, g_wc); cudaGetSymbolAddress((void**)&bc, g_bc);
    cudaGetSymbolAddress((void**)&hpsum, g_hpsum); cudaGetSymbolAddress((void**)&hpsq, g_hpsq);

    const int DN = Dm*Nn;
    wc_kernel<<<dim3(1,4,4), 256>>>(W1, Wm, wc);
    bc_kernel<<<4, 256>>>(W1, bm, b1, bc);
    init_kernel<<<(Bsz*DN/4)/256, 256>>>((const float4*)x0in, (const float4*)x1in,
                                         (float4*)x, idx);

    const int Ks[4] = {2048, 1024, 512, 256};
    for (int l = 0; l < 4; l++) {
        int K = Ks[l], cross = (l & 1), DK = Dm*K;
        int doimp = (l < 3);

        const float* sArg = s;
        if (l == 0) {
            sArg = x;   // identity idx + 'self': s == x exactly
        } else {
            gather_kernel<<<(Zs*DK)/256, 256>>>(x, idx, s, K, cross);
        }

        qkv_kernel<<<dim3(Nn/128, 1, 12), 256>>>(
            Wq+(size_t)l*Dm*Dm, bq+l*Dm, Wk+(size_t)l*Dm*Dm, bk+l*Dm,
            Wv+(size_t)l*Dm*Dm, bv+l*Dm, x, sArg, q, k, v, K);

        scores2_kernel<<<dim3(K/128, Nn/128, ZH), 256>>>(q, k, sc, pm, pz, K);
        msg5_kernel<<<dim3(Nn/128, ZH), 256>>>(sc, v, pm, pz, msg, impp, K, doimp);

        if (doimp) {
            impreduce_kernel<<<(Zs*K+255)/256, 256>>>(impp, imp, K);
            rankflag_kernel<<<dim3(K/128, Zs), 128>>>(imp, flag, K, K/2);
        }

        w1dual_kernel<<<dim3(Nn/128, 2, Zs), 256>>>(
            W1+(size_t)l*2*Dm*2*Dm, wc+(size_t)l*2*Dm*Dm, bc+l*2*Dm, x, msg, h,
            hpsum, hpsq);
        w2norm_kernel<<<dim3(Nn/128, 2, Zs), 256>>>(W2+(size_t)l*Dm*2*Dm, b2+l*Dm,
                                                    h, hpsum, hpsq, x);

        if (doimp)
            compact_kernel<<<Zs, 256>>>(flag, idx, K, cross);
    }

    copyf4_kernel<<<(Zs*DN/4+255)/256, 256>>>((const float4*)x, (float4*)out, Zs*DN/4);
}

// round 17
// speedup vs baseline: 1.0357x; 1.0357x over previous
#include <cuda_runtime.h>
#include <cuda_fp16.h>
#include <math.h>

#define Bsz 2
#define Dm  128
#define Nn  2048
#define Hh  4
#define Zs  4
#define ZH  16
typedef unsigned long long u64;

__device__ float  g_x [Zs*Dm*Nn];
__device__ float  g_s [Zs*Dm*Nn];
__device__ float  g_q [Zs*Dm*Nn];
__device__ float  g_k [Zs*Dm*Nn];
__device__ float  g_v [Zs*Dm*Nn];
__device__ __half g_sc[(size_t)ZH*Nn*Nn];
__device__ float  g_pm[ZH*16*Nn];
__device__ float  g_pz[ZH*16*Nn];
__device__ float  g_msg[Zs*Dm*Nn];
__device__ float  g_h [Zs*2*Dm*Nn];
__device__ float  g_impp[ZH*16*Nn];
__device__ float  g_imp[Zs*Nn];
__device__ int    g_idx[Zs*Nn];
__device__ int    g_flag[Zs*Nn];
__device__ float  g_wc[4*256*128];
__device__ float  g_bc[4*256];
__device__ float  g_hpsum[Zs*256*16];
__device__ float  g_hpsq [Zs*256*16];

__device__ __forceinline__ u64 ffma2(u64 a, u64 b, u64 c) {
    u64 d; asm("fma.rn.f32x2 %0, %1, %2, %3;" : "=l"(d) : "l"(a), "l"(b), "l"(c)); return d;
}
__device__ __forceinline__ u64 dupf(float x) {
    u64 d; unsigned xi = __float_as_uint(x);
    asm("mov.b64 %0, {%1, %2};" : "=l"(d) : "r"(xi), "r"(xi)); return d;
}
__device__ __forceinline__ float2 unpk(u64 v) {
    unsigned lo, hi; asm("mov.b64 {%0, %1}, %2;" : "=r"(lo), "=r"(hi) : "l"(v));
    return make_float2(__uint_as_float(lo), __uint_as_float(hi));
}

__global__ void copyf4_kernel(const float4* __restrict__ s, float4* __restrict__ d, int n4)
{ int g = blockIdx.x*256 + threadIdx.x; if (g < n4) d[g] = s[g]; }

__global__ void init_kernel(const float4* __restrict__ x0, const float4* __restrict__ x1,
                            float4* __restrict__ x, int* __restrict__ idx)
{
    int g = blockIdx.x*256 + threadIdx.x;
    x[g] = x0[g];
    x[g + Bsz*Dm*Nn/4] = x1[g];
    if (g < Zs*Nn) idx[g] = g % Nn;
}

__global__ void gather_kernel(const float* __restrict__ x, const int* __restrict__ idx,
                              float* __restrict__ s, int K, int cross)
{
    int g = blockIdx.x*256 + threadIdx.x;
    if (g >= Zs*Dm*K) return;
    int z = g / (Dm*K), r = g - z*(Dm*K);
    int d = r / K, kk = r - d*K;
    int zs = (((z>>1) ^ cross) << 1) | (z & 1);
    s[g] = x[(size_t)zs*Dm*Nn + (size_t)d*Nn + idx[zs*Nn + kk]];
}

// ---------------- core 128co x 128n GEMM, BK=32 ----------------
__device__ __forceinline__ void pw3_core(
    const float* W, const float* X,
    const float* bias, float* Y, int Ncols, int n0)
{
    __shared__ float As[32][132];
    __shared__ float Bs[32][132];
    int tid = threadIdx.x, ty = tid >> 4, tx = tid & 15;
    u64 acc[8][4];
    #pragma unroll
    for (int i = 0; i < 8; i++) { acc[i][0]=0; acc[i][1]=0; acc[i][2]=0; acc[i][3]=0; }

    for (int kt = 0; kt < Dm; kt += 32) {
        #pragma unroll
        for (int j = 0; j < 4; j++) {
            int e = tid + 256*j, r = e >> 3, kq = e & 7;
            float4 w4 = *(const float4*)&W[(size_t)r*Dm + kt + kq*4];
            As[kq*4+0][r]=w4.x; As[kq*4+1][r]=w4.y; As[kq*4+2][r]=w4.z; As[kq*4+3][r]=w4.w;
        }
        #pragma unroll
        for (int j = 0; j < 4; j++) {
            int e = tid + 256*j, kr = e >> 5, c4 = e & 31;
            *(float4*)&Bs[kr][c4*4] = *(const float4*)&X[(size_t)(kt+kr)*Ncols + n0 + c4*4];
        }
        __syncthreads();
        #pragma unroll
        for (int kk = 0; kk < 32; kk++) {
            float4 a0 = *(const float4*)&As[kk][ty*8];
            float4 a1 = *(const float4*)&As[kk][ty*8+4];
            ulonglong2 bA = *(const ulonglong2*)&Bs[kk][tx*8];
            ulonglong2 bB = *(const ulonglong2*)&Bs[kk][tx*8+4];
            float ar[8] = {a0.x,a0.y,a0.z,a0.w,a1.x,a1.y,a1.z,a1.w};
            #pragma unroll
            for (int r = 0; r < 8; r++) {
                u64 a2 = dupf(ar[r]);
                acc[r][0] = ffma2(a2, bA.x, acc[r][0]);
                acc[r][1] = ffma2(a2, bA.y, acc[r][1]);
                acc[r][2] = ffma2(a2, bB.x, acc[r][2]);
                acc[r][3] = ffma2(a2, bB.y, acc[r][3]);
            }
        }
        __syncthreads();
    }
    #pragma unroll
    for (int r = 0; r < 8; r++) {
        int row = ty*8 + r;
        float bi = bias[row];
        float2 o0=unpk(acc[r][0]), o1=unpk(acc[r][1]), o2=unpk(acc[r][2]), o3=unpk(acc[r][3]);
        float4 u = make_float4(o0.x+bi, o0.y+bi, o1.x+bi, o1.y+bi);
        float4 w = make_float4(o2.x+bi, o2.y+bi, o3.x+bi, o3.y+bi);
        float* dst = Y + (size_t)row*Ncols + n0 + tx*8;
        *(float4*)dst = u; *(float4*)(dst+4) = w;
    }
}

// merged q/k/v projection. grid (Nn/128, 1, 12), forced 2 blocks/SM
__global__ void __launch_bounds__(256, 2) qkv_kernel(
    const float* __restrict__ Wq, const float* __restrict__ bq,
    const float* __restrict__ Wk, const float* __restrict__ bk,
    const float* __restrict__ Wv, const float* __restrict__ bv,
    const float* __restrict__ x, const float* __restrict__ s,
    float* __restrict__ q, float* __restrict__ k, float* __restrict__ v, int K)
{
    int which = blockIdx.z >> 2, z = blockIdx.z & 3;
    int n0 = blockIdx.x*128;
    const float *W, *bias, *X; float* Y; int NC;
    if (which == 0)      { W=Wq; bias=bq; X=x+(size_t)z*Dm*Nn; Y=q+(size_t)z*Dm*Nn; NC=Nn; }
    else if (which == 1) { if (n0 >= K) return; W=Wk; bias=bk; X=s+(size_t)z*Dm*K; Y=k+(size_t)z*Dm*K; NC=K; }
    else                 { if (n0 >= K) return; W=Wv; bias=bv; X=s+(size_t)z*Dm*K; Y=v+(size_t)z*Dm*K; NC=K; }
    pw3_core(W, X, bias, Y, NC, n0);
}

// Wc[l] = W1b[l] @ Wm[l].  grid (1, 4, 4), 64co x 128n
__global__ void __launch_bounds__(256) wc_kernel(
    const float* __restrict__ W1, const float* __restrict__ Wm, float* __restrict__ wc)
{
    __shared__ float As[32][68];
    __shared__ float Bs[32][132];
    int l = blockIdx.z, co0 = blockIdx.y*64;
    const float* W = W1 + (size_t)l*2*Dm*2*Dm + Dm;
    const float* X = Wm + (size_t)l*Dm*Dm;
    float* Y = wc + (size_t)l*2*Dm*Dm;
    int tid = threadIdx.x, ty = tid >> 4, tx = tid & 15;
    u64 c2[4][4];
    #pragma unroll
    for (int i = 0; i < 4; i++) { c2[i][0]=0; c2[i][1]=0; c2[i][2]=0; c2[i][3]=0; }
    for (int kt = 0; kt < Dm; kt += 32) {
        #pragma unroll
        for (int j = 0; j < 2; j++) {
            int e = tid + 256*j, r = e >> 3, kq = e & 7;
            float4 w4 = *(const float4*)&W[(size_t)(co0+r)*2*Dm + kt + kq*4];
            As[kq*4+0][r]=w4.x; As[kq*4+1][r]=w4.y; As[kq*4+2][r]=w4.z; As[kq*4+3][r]=w4.w;
        }
        #pragma unroll
        for (int j = 0; j < 4; j++) {
            int e = tid + 256*j, kr = e >> 5, c4 = e & 31;
            *(float4*)&Bs[kr][c4*4] = *(const float4*)&X[(size_t)(kt+kr)*Dm + c4*4];
        }
        __syncthreads();
        #pragma unroll
        for (int kk = 0; kk < 32; kk++) {
            float4 a4 = *(const float4*)&As[kk][ty*4];
            ulonglong2 bA = *(const ulonglong2*)&Bs[kk][tx*8];
            ulonglong2 bB = *(const ulonglong2*)&Bs[kk][tx*8+4];
            float ar[4] = {a4.x, a4.y, a4.z, a4.w};
            #pragma unroll
            for (int r = 0; r < 4; r++) {
                u64 a2 = dupf(ar[r]);
                c2[r][0] = ffma2(a2, bA.x, c2[r][0]);
                c2[r][1] = ffma2(a2, bA.y, c2[r][1]);
                c2[r][2] = ffma2(a2, bB.x, c2[r][2]);
                c2[r][3] = ffma2(a2, bB.y, c2[r][3]);
            }
        }
        __syncthreads();
    }
    #pragma unroll
    for (int r = 0; r < 4; r++) {
        int row = co0 + ty*4 + r;
        float2 o0=unpk(c2[r][0]), o1=unpk(c2[r][1]), o2=unpk(c2[r][2]), o3=unpk(c2[r][3]);
        float* dst = Y + (size_t)row*Dm + tx*8;
        *(float4*)dst     = make_float4(o0.x, o0.y, o1.x, o1.y);
        *(float4*)(dst+4) = make_float4(o2.x, o2.y, o3.x, o3.y);
    }
}

__global__ void bc_kernel(const float* __restrict__ W1, const float* __restrict__ bm,
                          const float* __restrict__ b1, float* __restrict__ bc)
{
    int l = blockIdx.x, o = threadIdx.x;
    const float* wrow = W1 + (size_t)l*2*Dm*2*Dm + (size_t)o*2*Dm + Dm;
    const float* bml = bm + l*Dm;
    float s = b1[l*2*Dm + o];
    #pragma unroll 4
    for (int j = 0; j < Dm; j++) s += wrow[j]*bml[j];
    bc[l*2*Dm + o] = s;
}

// h_pre = W1a@x + Wc@msg + bc with per-row (sum, sumsq) partials. grid (Nn/128, 2, Zs)
__global__ void __launch_bounds__(256) w1dual_kernel(
    const float* __restrict__ W1, const float* __restrict__ Wc,
    const float* __restrict__ bc,
    const float* __restrict__ x, const float* __restrict__ msg, float* __restrict__ h,
    float* __restrict__ hpsum, float* __restrict__ hpsq)
{
    __shared__ float As[32][132];
    __shared__ float Bs[32][132];
    __shared__ float redS[128][17];
    __shared__ float redQ[128][17];
    int z = blockIdx.z, co0 = blockIdx.y*128, n0 = blockIdx.x*128;
    const float* Xa = x   + (size_t)z*Dm*Nn;
    const float* Xb = msg + (size_t)z*Dm*Nn;
    float* Y = h + (size_t)z*2*Dm*Nn;
    int tid = threadIdx.x, ty = tid >> 4, tx = tid & 15;
    u64 acc[8][4];
    #pragma unroll
    for (int i = 0; i < 8; i++) { acc[i][0]=0; acc[i][1]=0; acc[i][2]=0; acc[i][3]=0; }

    for (int kt = 0; kt < 2*Dm; kt += 32) {
        const float* W = (kt < Dm) ? W1 : Wc;
        const float* X = (kt < Dm) ? Xa : Xb;
        int ws = (kt < Dm) ? 2*Dm : Dm;
        int kl = (kt < Dm) ? kt : (kt - Dm);
        #pragma unroll
        for (int j = 0; j < 4; j++) {
            int e = tid + 256*j, r = e >> 3, kq = e & 7;
            float4 w4 = *(const float4*)&W[(size_t)(co0+r)*ws + kl + kq*4];
            As[kq*4+0][r]=w4.x; As[kq*4+1][r]=w4.y; As[kq*4+2][r]=w4.z; As[kq*4+3][r]=w4.w;
        }
        #pragma unroll
        for (int j = 0; j < 4; j++) {
            int e = tid + 256*j, kr = e >> 5, c4 = e & 31;
            *(float4*)&Bs[kr][c4*4] = *(const float4*)&X[(size_t)(kl+kr)*Nn + n0 + c4*4];
        }
        __syncthreads();
        #pragma unroll
        for (int kk = 0; kk < 32; kk++) {
            float4 a0 = *(const float4*)&As[kk][ty*8];
            float4 a1 = *(const float4*)&As[kk][ty*8+4];
            ulonglong2 bA = *(const ulonglong2*)&Bs[kk][tx*8];
            ulonglong2 bB = *(const ulonglong2*)&Bs[kk][tx*8+4];
            float ar[8] = {a0.x,a0.y,a0.z,a0.w,a1.x,a1.y,a1.z,a1.w};
            #pragma unroll
            for (int r = 0; r < 8; r++) {
                u64 a2 = dupf(ar[r]);
                acc[r][0] = ffma2(a2, bA.x, acc[r][0]);
                acc[r][1] = ffma2(a2, bA.y, acc[r][1]);
                acc[r][2] = ffma2(a2, bB.x, acc[r][2]);
                acc[r][3] = ffma2(a2, bB.y, acc[r][3]);
            }
        }
        __syncthreads();
    }
    #pragma unroll
    for (int r = 0; r < 8; r++) {
        int row = co0 + ty*8 + r;
        float bi = bc[row];
        float2 o0=unpk(acc[r][0]), o1=unpk(acc[r][1]), o2=unpk(acc[r][2]), o3=unpk(acc[r][3]);
        float4 u = make_float4(o0.x+bi, o0.y+bi, o1.x+bi, o1.y+bi);
        float4 w = make_float4(o2.x+bi, o2.y+bi, o3.x+bi, o3.y+bi);
        float* dst = Y + (size_t)row*Nn + n0 + tx*8;
        *(float4*)dst = u; *(float4*)(dst+4) = w;
        float ss = u.x+u.y+u.z+u.w + w.x+w.y+w.z+w.w;
        float qq = u.x*u.x+u.y*u.y+u.z*u.z+u.w*u.w + w.x*w.x+w.y*w.y+w.z*w.z+w.w*w.w;
        redS[ty*8+r][tx] = ss;
        redQ[ty*8+r][tx] = qq;
    }
    __syncthreads();
    if (tid < 128) {
        float ss = 0.f, qq = 0.f;
        #pragma unroll
        for (int t = 0; t < 16; t++) { ss += redS[tid][t]; qq += redQ[tid][t]; }
        int row = co0 + tid;
        hpsum[((size_t)z*256 + row)*16 + blockIdx.x] = ss;
        hpsq [((size_t)z*256 + row)*16 + blockIdx.x] = qq;
    }
}

// x += W2 @ relu((h-mean)*rs) + b2, inline stat finalize. grid (Nn/128, 2, Zs)
__global__ void __launch_bounds__(256) w2norm_kernel(
    const float* __restrict__ W2, const float* __restrict__ b2,
    const float* __restrict__ h, const float* __restrict__ hpsum,
    const float* __restrict__ hpsq, float* __restrict__ x)
{
    __shared__ float As[32][68];
    __shared__ float Bs[32][132];
    __shared__ float sMean[256], sRs[256];
    int z = blockIdx.z;
    const float* Xb = h + (size_t)z*2*Dm*Nn;
    float*       Yb = x + (size_t)z*Dm*Nn;
    int co0 = blockIdx.y*64, n0 = blockIdx.x*128;
    int tid = threadIdx.x, ty = tid >> 4, tx = tid & 15;
    {
        const float* ps = hpsum + ((size_t)z*256 + tid)*16;
        const float* pq = hpsq  + ((size_t)z*256 + tid)*16;
        float ss = 0.f, qq = 0.f;
        #pragma unroll
        for (int t = 0; t < 16; t++) { ss += ps[t]; qq += pq[t]; }
        float mean = ss * (1.0f/Nn);
        sMean[tid] = mean;
        sRs[tid]   = rsqrtf(qq*(1.0f/Nn) - mean*mean + 1e-3f);
    }
    __syncthreads();
    u64 c2[4][4];
    #pragma unroll
    for (int i = 0; i < 4; i++) { c2[i][0]=0; c2[i][1]=0; c2[i][2]=0; c2[i][3]=0; }
    for (int kt = 0; kt < 2*Dm; kt += 32) {
        #pragma unroll
        for (int j = 0; j < 2; j++) {
            int e = tid + 256*j, r = e >> 3, kq = e & 7;
            float4 w4 = *(const float4*)&W2[(size_t)(co0+r)*2*Dm + kt + kq*4];
            As[kq*4+0][r]=w4.x; As[kq*4+1][r]=w4.y; As[kq*4+2][r]=w4.z; As[kq*4+3][r]=w4.w;
        }
        #pragma unroll
        for (int j = 0; j < 4; j++) {
            int e = tid + 256*j, kr = e >> 5, c4 = e & 31;
            int hrow = kt + kr;
            float4 raw = *(const float4*)&Xb[(size_t)hrow*Nn + n0 + c4*4];
            float mean = sMean[hrow], rs = sRs[hrow];
            Bs[kr][c4*4+0] = fmaxf((raw.x-mean)*rs, 0.f);
            Bs[kr][c4*4+1] = fmaxf((raw.y-mean)*rs, 0.f);
            Bs[kr][c4*4+2] = fmaxf((raw.z-mean)*rs, 0.f);
            Bs[kr][c4*4+3] = fmaxf((raw.w-mean)*rs, 0.f);
        }
        __syncthreads();
        #pragma unroll
        for (int kk = 0; kk < 32; kk++) {
            float4 a4 = *(const float4*)&As[kk][ty*4];
            ulonglong2 bA = *(const ulonglong2*)&Bs[kk][tx*8];
            ulonglong2 bB = *(const ulonglong2*)&Bs[kk][tx*8+4];
            float ar[4] = {a4.x, a4.y, a4.z, a4.w};
            #pragma unroll
            for (int r = 0; r < 4; r++) {
                u64 a2 = dupf(ar[r]);
                c2[r][0] = ffma2(a2, bA.x, c2[r][0]);
                c2[r][1] = ffma2(a2, bA.y, c2[r][1]);
                c2[r][2] = ffma2(a2, bB.x, c2[r][2]);
                c2[r][3] = ffma2(a2, bB.y, c2[r][3]);
            }
        }
        __syncthreads();
    }
    #pragma unroll
    for (int r = 0; r < 4; r++) {
        int row = co0 + ty*4 + r;
        float bi = b2[row];
        float2 o0=unpk(c2[r][0]), o1=unpk(c2[r][1]), o2=unpk(c2[r][2]), o3=unpk(c2[r][3]);
        float4 u = make_float4(o0.x+bi, o0.y+bi, o1.x+bi, o1.y+bi);
        float4 w = make_float4(o2.x+bi, o2.y+bi, o3.x+bi, o3.y+bi);
        float* dst = Yb + (size_t)row*Nn + n0 + tx*8;
        float4 e0 = *(float4*)dst, e1 = *(float4*)(dst+4);
        u.x+=e0.x; u.y+=e0.y; u.z+=e0.z; u.w+=e0.w;
        w.x+=e1.x; w.y+=e1.y; w.z+=e1.z; w.w+=e1.w;
        *(float4*)dst = u; *(float4*)(dst+4) = w;
    }
}

// scores: 128n x 128k tile; stores fp16 exp numerators + (m_tile, sumexp)
__global__ void __launch_bounds__(256) scores2_kernel(
    const float* __restrict__ q, const float* __restrict__ kbuf,
    __half* __restrict__ sc, float* __restrict__ pm, float* __restrict__ pz, int K)
{
    __shared__ float Qs[32][128];
    __shared__ float Ks[32][128];
    __shared__ float red[128][17];
    __shared__ float rowm[128];
    int zh = blockIdx.z, z = zh >> 2, h = zh & 3;
    int n0 = blockIdx.y*128, k0 = blockIdx.x*128;
    const float* qb = q    + (size_t)z*Dm*Nn;
    const float* kb = kbuf + (size_t)z*Dm*K;
    int tid = threadIdx.x;
    #pragma unroll
    for (int j = 0; j < 4; j++) {
        int e = tid + 256*j, i = e >> 5, c4 = e & 31;
        *(float4*)&Qs[i][c4*4] = *(const float4*)&qb[(size_t)(i*4+h)*Nn + n0 + c4*4];
        *(float4*)&Ks[i][c4*4] = *(const float4*)&kb[(size_t)(i*4+h)*K  + k0 + c4*4];
    }
    __syncthreads();
    int ty = tid >> 4, tx = tid & 15, r0 = ty*8, c0 = tx*8;
    u64 acc[8][4];
    #pragma unroll
    for (int i = 0; i < 8; i++) { acc[i][0]=0; acc[i][1]=0; acc[i][2]=0; acc[i][3]=0; }
    #pragma unroll
    for (int i = 0; i < 32; i++) {
        float4 a0 = *(const float4*)&Qs[i][r0];
        float4 a1 = *(const float4*)&Qs[i][r0+4];
        ulonglong2 bA = *(const ulonglong2*)&Ks[i][c0];
        ulonglong2 bB = *(const ulonglong2*)&Ks[i][c0+4];
        float ar[8] = {a0.x,a0.y,a0.z,a0.w,a1.x,a1.y,a1.z,a1.w};
        #pragma unroll
        for (int r = 0; r < 8; r++) {
            u64 a2 = dupf(ar[r]);
            acc[r][0] = ffma2(a2, bA.x, acc[r][0]);
            acc[r][1] = ffma2(a2, bA.y, acc[r][1]);
            acc[r][2] = ffma2(a2, bB.x, acc[r][2]);
            acc[r][3] = ffma2(a2, bB.y, acc[r][3]);
        }
    }
    const float scale = 0.17677669529663687f;
    __half* scb = sc + (size_t)zh*Nn*K;
    float vals[8][8], vmax[8];
    #pragma unroll
    for (int r = 0; r < 8; r++) {
        float2 p0=unpk(acc[r][0]), p1=unpk(acc[r][1]), p2=unpk(acc[r][2]), p3=unpk(acc[r][3]);
        vals[r][0]=p0.x*scale; vals[r][1]=p0.y*scale; vals[r][2]=p1.x*scale; vals[r][3]=p1.y*scale;
        vals[r][4]=p2.x*scale; vals[r][5]=p2.y*scale; vals[r][6]=p3.x*scale; vals[r][7]=p3.y*scale;
        float m = vals[r][0];
        #pragma unroll
        for (int c = 1; c < 8; c++) m = fmaxf(m, vals[r][c]);
        vmax[r] = m;
    }
    #pragma unroll
    for (int r = 0; r < 8; r++) red[r0+r][tx] = vmax[r];
    __syncthreads();
    if (tid < 128) {
        float m = red[tid][0];
        #pragma unroll
        for (int t = 1; t < 16; t++) m = fmaxf(m, red[tid][t]);
        rowm[tid] = m;
    }
    __syncthreads();
    #pragma unroll
    for (int r = 0; r < 8; r++) {
        float m = rowm[r0+r], s = 0.0f;
        float ev[8];
        #pragma unroll
        for (int c = 0; c < 8; c++) { ev[c] = expf(vals[r][c] - m); s += ev[c]; }
        __half2 hp[4];
        hp[0] = __floats2half2_rn(ev[0], ev[1]);
        hp[1] = __floats2half2_rn(ev[2], ev[3]);
        hp[2] = __floats2half2_rn(ev[4], ev[5]);
        hp[3] = __floats2half2_rn(ev[6], ev[7]);
        *(uint4*)&scb[(size_t)(n0+r0+r)*K + k0 + c0] = *(uint4*)hp;
        red[r0+r][tx] = s;
    }
    __syncthreads();
    if (tid < 128) {
        float s = 0.0f;
        #pragma unroll
        for (int t = 0; t < 16; t++) s += red[tid][t];
        size_t po = ((size_t)zh*gridDim.x + blockIdx.x)*Nn + n0 + tid;
        pm[po] = rowm[tid]; pz[po] = s;
    }
}

// msg + inline combine + importance; fp16 sc reads, 256 threads, split-K
__global__ void __launch_bounds__(256) msg5_kernel(
    const __half* __restrict__ sc, const float* __restrict__ v,
    const float* __restrict__ pm, const float* __restrict__ pz,
    float* __restrict__ msg, float* __restrict__ impp, int K, int doimp)
{
    __shared__ float Ps[128][36];
    __shared__ float Vs[32][36];
    __shared__ float cred2[64][32];
    __shared__ float sf[128][17];
    int zh = blockIdx.y, z = zh >> 2, h = zh & 3;
    int n0 = blockIdx.x*128;
    int tid = threadIdx.x;
    int PT = K >> 7;
    const __half* scb = sc + (size_t)zh*Nn*K;
    const float*  vb  = v  + (size_t)z*Dm*K;
    if (tid < 128) {
        float m = -1e30f;
        for (int pt = 0; pt < PT; pt++)
            m = fmaxf(m, pm[((size_t)zh*PT + pt)*Nn + n0 + tid]);
        float s = 0.0f;
        for (int pt = 0; pt < PT; pt++)
            s += pz[((size_t)zh*PT + pt)*Nn + n0 + tid] *
                 expf(pm[((size_t)zh*PT + pt)*Nn + n0 + tid] - m);
        float iz = 1.0f / s;
        for (int pt = 0; pt < PT; pt++)
            sf[tid][pt] = expf(pm[((size_t)zh*PT + pt)*Nn + n0 + tid] - m) * iz;
    }
    __syncthreads();
    int rg2 = tid >> 2, kq = tid & 3;          // staging: rows rg2+64j, k's kq*8..+7
    int lt = tid & 127, kh = tid >> 7;
    int ty = lt >> 2, tx = lt & 3;
    u64 c2[4][4];
    #pragma unroll
    for (int i = 0; i < 4; i++) { c2[i][0]=0; c2[i][1]=0; c2[i][2]=0; c2[i][3]=0; }

    for (int kc = 0; kc < K; kc += 32) {
        int pt = kc >> 7;
        float cs[8] = {0.f,0.f,0.f,0.f,0.f,0.f,0.f,0.f};
        #pragma unroll
        for (int j = 0; j < 2; j++) {
            int row = rg2 + 64*j;
            uint4 raw = *(const uint4*)&scb[(size_t)(n0+row)*K + kc + kq*8];
            __half2* hp = (__half2*)&raw;
            float f = sf[row][pt];
            float2 t0 = __half22float2(hp[0]);
            float2 t1 = __half22float2(hp[1]);
            float2 t2 = __half22float2(hp[2]);
            float2 t3 = __half22float2(hp[3]);
            float p0=t0.x*f, p1=t0.y*f, p2=t1.x*f, p3=t1.y*f;
            float p4=t2.x*f, p5=t2.y*f, p6=t3.x*f, p7=t3.y*f;
            *(float4*)&Ps[row][kq*8]   = make_float4(p0,p1,p2,p3);
            *(float4*)&Ps[row][kq*8+4] = make_float4(p4,p5,p6,p7);
            cs[0]+=p0; cs[1]+=p1; cs[2]+=p2; cs[3]+=p3;
            cs[4]+=p4; cs[5]+=p5; cs[6]+=p6; cs[7]+=p7;
        }
        if (doimp) {
            #pragma unroll
            for (int c = 0; c < 8; c++) cred2[rg2][kq*8 + c] = cs[c];
        }
        {
            int d = tid >> 3, kq8 = tid & 7;
            float4 v4 = *(const float4*)&vb[(size_t)(d*4+h)*K + kc + kq8*4];
            Vs[kq8*4+0][d]=v4.x; Vs[kq8*4+1][d]=v4.y; Vs[kq8*4+2][d]=v4.z; Vs[kq8*4+3][d]=v4.w;
        }
        __syncthreads();
        if (doimp && tid < 32) {
            float ssum = 0.0f;
            #pragma unroll 8
            for (int g2 = 0; g2 < 64; g2++) ssum += cred2[g2][tid];
            impp[((size_t)zh*(Nn/128) + blockIdx.x)*K + kc + tid] = ssum;
        }
        #pragma unroll
        for (int kk4 = 0; kk4 < 4; kk4++) {
            int k4 = kh*4 + kk4;
            ulonglong2 va[4], vb2[4];
            #pragma unroll
            for (int c = 0; c < 4; c++) {
                va[c]  = *(const ulonglong2*)&Vs[k4*4+c][tx*8];
                vb2[c] = *(const ulonglong2*)&Vs[k4*4+c][tx*8+4];
            }
            #pragma unroll
            for (int r = 0; r < 4; r++) {
                float4 pr = *(const float4*)&Ps[ty + 32*r][k4*4];
                float pv[4] = {pr.x, pr.y, pr.z, pr.w};
                #pragma unroll
                for (int c = 0; c < 4; c++) {
                    u64 a2 = dupf(pv[c]);
                    c2[r][0] = ffma2(a2, va[c].x,  c2[r][0]);
                    c2[r][1] = ffma2(a2, va[c].y,  c2[r][1]);
                    c2[r][2] = ffma2(a2, vb2[c].x, c2[r][2]);
                    c2[r][3] = ffma2(a2, vb2[c].y, c2[r][3]);
                }
            }
        }
        __syncthreads();
    }
    float* mbuf = &Ps[0][0];
    if (kh == 1) {
        #pragma unroll
        for (int r = 0; r < 4; r++)
            #pragma unroll
            for (int c = 0; c < 4; c++) {
                float2 p = unpk(c2[r][c]);
                mbuf[lt*33 + (r*4+c)*2 + 0] = p.x;
                mbuf[lt*33 + (r*4+c)*2 + 1] = p.y;
            }
    }
    __syncthreads();
    if (kh == 0) {
        #pragma unroll
        for (int r = 0; r < 4; r++) {
            float2 q0=unpk(c2[r][0]), q1=unpk(c2[r][1]), q2=unpk(c2[r][2]), q3=unpk(c2[r][3]);
            float ov[8] = {q0.x,q0.y,q1.x,q1.y,q2.x,q2.y,q3.x,q3.y};
            #pragma unroll
            for (int c = 0; c < 8; c++) {
                float oth = mbuf[lt*33 + (r*4 + (c>>1))*2 + (c&1)];
                int d = (tx*8 + c)*4 + h;
                msg[(size_t)z*Dm*Nn + (size_t)d*Nn + n0 + ty + 32*r] = ov[c] + oth;
            }
        }
    }
}

__global__ void impreduce_kernel(const float* __restrict__ impp, float* __restrict__ imp, int K)
{
    int g = blockIdx.x*256 + threadIdx.x;
    if (g >= Zs*K) return;
    int z = g / K, k = g - z*K;
    float s = 0.0f;
    for (int h = 0; h < Hh; h++)
        for (int nb = 0; nb < Nn/128; nb++)
            s += impp[((size_t)((z*4+h)*(Nn/128) + nb))*K + k];
    imp[z*Nn + k] = s;
}

__global__ void rankflag_kernel(const float* __restrict__ imp, int* __restrict__ flag,
                                int K, int kkeep)
{
    __shared__ float sp[2048];
    int z = blockIdx.y;
    int tid = threadIdx.x;
    int pos = blockIdx.x*128 + tid;
    for (int j = tid; j < K; j += 128) sp[j] = imp[z*Nn + j];
    __syncthreads();
    float vv = sp[pos];
    int r = 0;
    for (int j = 0; j < K; j++) {
        float u = sp[j];
        r += (u > vv) || (u == vv && j < pos);
    }
    flag[z*Nn + pos] = (r < kkeep) ? 1 : 0;
}

__global__ void compact_kernel(const int* __restrict__ flag, int* __restrict__ idx,
                               int K, int cross)
{
    __shared__ int sflag[2048];
    __shared__ int sidx[2048];
    __shared__ int scnt[256];
    int z = blockIdx.x;
    int tz = (((z>>1) ^ cross) << 1) | (z & 1);
    int* ix = idx + (size_t)tz*Nn;
    int tid = threadIdx.x;
    for (int j = tid; j < K; j += 256) { sflag[j] = flag[z*Nn + j]; sidx[j] = ix[j]; }
    __syncthreads();
    int chunk = K >> 8;
    int base = tid*chunk, c = 0;
    for (int t = 0; t < chunk; t++) c += sflag[base + t];
    scnt[tid] = c;
    __syncthreads();
    if (tid == 0) {
        int a = 0;
        for (int i = 0; i < 256; i++) { int t = scnt[i]; scnt[i] = a; a += t; }
    }
    __syncthreads();
    int o = scnt[tid];
    for (int t = 0; t < chunk; t++)
        if (sflag[base + t]) ix[o++] = sidx[base + t];
}

extern "C" void kernel_launch(void* const* d_in, const int* in_sizes, int n_in,
                              void* d_out, int out_size)
{
    const float* x0in = (const float*)d_in[0];
    const float* x1in = (const float*)d_in[1];
    const float* Wq = (const float*)d_in[2];  const float* bq = (const float*)d_in[3];
    const float* Wk = (const float*)d_in[4];  const float* bk = (const float*)d_in[5];
    const float* Wv = (const float*)d_in[6];  const float* bv = (const float*)d_in[7];
    const float* Wm = (const float*)d_in[8];  const float* bm = (const float*)d_in[9];
    const float* W1 = (const float*)d_in[10]; const float* b1 = (const float*)d_in[11];
    const float* W2 = (const float*)d_in[12]; const float* b2 = (const float*)d_in[13];
    float* out = (float*)d_out;

    float *x,*s,*q,*k,*v,*pm,*pz,*msg,*h,*impp,*imp,*wc,*bc,*hpsum,*hpsq;
    __half* sc;
    int *idx,*flag;
    cudaGetSymbolAddress((void**)&x, g_x);   cudaGetSymbolAddress((void**)&s, g_s);
    cudaGetSymbolAddress((void**)&q, g_q);   cudaGetSymbolAddress((void**)&k, g_k);
    cudaGetSymbolAddress((void**)&v, g_v);   cudaGetSymbolAddress((void**)&sc, g_sc);
    cudaGetSymbolAddress((void**)&pm, g_pm); cudaGetSymbolAddress((void**)&pz, g_pz);
    cudaGetSymbolAddress((void**)&msg, g_msg);
    cudaGetSymbolAddress((void**)&h, g_h);   cudaGetSymbolAddress((void**)&impp, g_impp);
    cudaGetSymbolAddress((void**)&imp, g_imp); cudaGetSymbolAddress((void**)&idx, g_idx);
    cudaGetSymbolAddress((void**)&flag, g_flag);
    cudaGetSymbolAddress((void**)&wc, g_wc); cudaGetSymbolAddress((void**)&bc, g_bc);
    cudaGetSymbolAddress((void**)&hpsum, g_hpsum); cudaGetSymbolAddress((void**)&hpsq, g_hpsq);

    const int DN = Dm*Nn;
    wc_kernel<<<dim3(1,4,4), 256>>>(W1, Wm, wc);
    bc_kernel<<<4, 256>>>(W1, bm, b1, bc);
    init_kernel<<<(Bsz*DN/4)/256, 256>>>((const float4*)x0in, (const float4*)x1in,
                                         (float4*)x, idx);

    const int Ks[4] = {2048, 1024, 512, 256};
    for (int l = 0; l < 4; l++) {
        int K = Ks[l], cross = (l & 1), DK = Dm*K;
        int doimp = (l < 3);

        const float* sArg = s;
        if (l == 0) {
            sArg = x;   // identity idx + 'self': s == x exactly
        } else {
            gather_kernel<<<(Zs*DK)/256, 256>>>(x, idx, s, K, cross);
        }

        qkv_kernel<<<dim3(Nn/128, 1, 12), 256>>>(
            Wq+(size_t)l*Dm*Dm, bq+l*Dm, Wk+(size_t)l*Dm*Dm, bk+l*Dm,
            Wv+(size_t)l*Dm*Dm, bv+l*Dm, x, sArg, q, k, v, K);

        scores2_kernel<<<dim3(K/128, Nn/128, ZH), 256>>>(q, k, sc, pm, pz, K);
        msg5_kernel<<<dim3(Nn/128, ZH), 256>>>(sc, v, pm, pz, msg, impp, K, doimp);

        if (doimp) {
            impreduce_kernel<<<(Zs*K+255)/256, 256>>>(impp, imp, K);
            rankflag_kernel<<<dim3(K/128, Zs), 128>>>(imp, flag, K, K/2);
        }

        w1dual_kernel<<<dim3(Nn/128, 2, Zs), 256>>>(
            W1+(size_t)l*2*Dm*2*Dm, wc+(size_t)l*2*Dm*Dm, bc+l*2*Dm, x, msg, h,
            hpsum, hpsq);
        w2norm_kernel<<<dim3(Nn/128, 2, Zs), 256>>>(W2+(size_t)l*Dm*2*Dm, b2+l*Dm,
                                                    h, hpsum, hpsq, x);

        if (doimp)
            compact_kernel<<<Zs, 256>>>(flag, idx, K, cross);
    }

    copyf4_kernel<<<(Zs*DN/4+255)/256, 256>>>((const float4*)x, (float4*)out, Zs*DN/4);
}